// round 2
// baseline (speedup 1.0000x reference)
#include <cuda_runtime.h>

#define N_NODES   100000
#define N_EDGES   1600000
#define N_FEAT    128
#define N_CLASSES 64
#define C4        (N_CLASSES / 4)   // 16 float4 per node row

// ---------------- scratch (device globals; no allocation) ----------------
__device__ float g_deg [N_NODES];
__device__ float g_dinv[N_NODES];
__device__ int2  g_edge[N_EDGES];            // (row, col) as int32
__device__ float g_norm[N_EDGES];            // dinv[row]*dinv[col]
__device__ float g_y0  [N_NODES * N_CLASSES]; // X @ W^T
__device__ float g_y1  [N_NODES * N_CLASSES]; // after hop 1
__device__ int   g_is64;

// vectorized global reduction (sm_90+)
__device__ __forceinline__ void red_add_v4(float4* p, float4 v) {
    asm volatile("red.global.add.v4.f32 [%0], {%1,%2,%3,%4};"
                 :: "l"(p), "f"(v.x), "f"(v.y), "f"(v.z), "f"(v.w)
                 : "memory");
}

// ---------------- dtype detection: int64 vs int32 edge_index ----------------
// Node ids < 2^31, so as int64 every high 32-bit word is 0. As int32, the odd
// words are random node ids (P(all 32 sampled == 0) ~ (1e-5)^32 ~ 0).
__global__ void k_detect(const int* __restrict__ ei32) {
    int ok = 1;
    #pragma unroll
    for (int i = 1; i < 64; i += 2) ok &= (ei32[i] == 0);
    g_is64 = ok;
}

// ---------------- degree / dinv ----------------
__global__ void k_deg_init() {
    int i = blockIdx.x * blockDim.x + threadIdx.x;
    if (i < N_NODES) g_deg[i] = 1.0f;   // self-loop
}

__global__ void k_deg_count(const void* __restrict__ eiv) {
    int e = blockIdx.x * blockDim.x + threadIdx.x;
    if (e >= N_EDGES) return;
    int c;
    if (g_is64) c = (int)((const long long*)eiv)[N_EDGES + e];
    else        c =       ((const int*)      eiv)[N_EDGES + e];
    atomicAdd(&g_deg[c], 1.0f);
}

__global__ void k_dinv() {
    int i = blockIdx.x * blockDim.x + threadIdx.x;
    if (i < N_NODES) g_dinv[i] = rsqrtf(g_deg[i]);
}

// ---------------- edge prep: int32 indices + per-edge norm ----------------
__global__ void k_prep(const void* __restrict__ eiv) {
    int e = blockIdx.x * blockDim.x + threadIdx.x;
    if (e >= N_EDGES) return;
    int r, c;
    if (g_is64) {
        const long long* p = (const long long*)eiv;
        r = (int)p[e]; c = (int)p[N_EDGES + e];
    } else {
        const int* p = (const int*)eiv;
        r = p[e];      c = p[N_EDGES + e];
    }
    g_edge[e] = make_int2(r, c);
    g_norm[e] = g_dinv[r] * g_dinv[c];
}

// ---------------- GEMM: Y0 = X @ W^T  (X: [N,128], W: [64,128]) ----------------
// Block = 256 threads, 16 nodes. W transposed into smem once per block.
__global__ __launch_bounds__(256) void k_gemm(const float* __restrict__ X,
                                              const float* __restrict__ W) {
    __shared__ float Ws[N_FEAT][N_CLASSES];   // 32 KB, Ws[k][c]
    __shared__ float xs[N_FEAT][17];          // 8.5 KB, xs[k][n] (pad: 17)
    const int t = threadIdx.x;

    // load W (64x128) transposed: thread i handles c=i>>5, float4 chunk k4=i&31
    for (int i = t; i < N_CLASSES * 32; i += 256) {
        int c = i >> 5, k4 = i & 31;
        float4 w = ((const float4*)(W + c * N_FEAT))[k4];
        Ws[k4 * 4 + 0][c] = w.x; Ws[k4 * 4 + 1][c] = w.y;
        Ws[k4 * 4 + 2][c] = w.z; Ws[k4 * 4 + 3][c] = w.w;
    }
    const int node0 = blockIdx.x * 16;
    // load 16 node rows (16x128) transposed
    for (int i = t; i < 16 * 32; i += 256) {
        int n = i >> 5, k4 = i & 31;
        float4 v = ((const float4*)(X + (size_t)(node0 + n) * N_FEAT))[k4];
        xs[k4 * 4 + 0][n] = v.x; xs[k4 * 4 + 1][n] = v.y;
        xs[k4 * 4 + 2][n] = v.z; xs[k4 * 4 + 3][n] = v.w;
    }
    __syncthreads();

    const int c  = t & 63;        // class
    const int ng = t >> 6;        // node group (4 nodes each)
    float a0 = 0.f, a1 = 0.f, a2 = 0.f, a3 = 0.f;
    #pragma unroll 8
    for (int k = 0; k < N_FEAT; k++) {
        float wv = Ws[k][c];
        a0 = fmaf(xs[k][ng * 4 + 0], wv, a0);
        a1 = fmaf(xs[k][ng * 4 + 1], wv, a1);
        a2 = fmaf(xs[k][ng * 4 + 2], wv, a2);
        a3 = fmaf(xs[k][ng * 4 + 3], wv, a3);
    }
    g_y0[(size_t)(node0 + ng * 4 + 0) * N_CLASSES + c] = a0;
    g_y0[(size_t)(node0 + ng * 4 + 1) * N_CLASSES + c] = a1;
    g_y0[(size_t)(node0 + ng * 4 + 2) * N_CLASSES + c] = a2;
    g_y0[(size_t)(node0 + ng * 4 + 3) * N_CLASSES + c] = a3;
}

// ---------------- hop 1 ----------------
__global__ void k_self1() {   // g_y1 = dinv^2 * g_y0
    int i = blockIdx.x * blockDim.x + threadIdx.x;   // over N_NODES*C4 float4
    if (i >= N_NODES * C4) return;
    int node = i >> 4;
    float s = g_dinv[node]; s *= s;
    float4 v = ((const float4*)g_y0)[i];
    v.x *= s; v.y *= s; v.z *= s; v.w *= s;
    ((float4*)g_y1)[i] = v;
}

__global__ void k_scat1() {   // g_y1[col] += norm * g_y0[row]
    int t = blockIdx.x * blockDim.x + threadIdx.x;
    int e = t >> 4;
    if (e >= N_EDGES) return;
    int lane = t & 15;
    int2  rc = g_edge[e];
    float nm = g_norm[e];
    float4 v = ((const float4*)g_y0)[rc.x * C4 + lane];
    v.x *= nm; v.y *= nm; v.z *= nm; v.w *= nm;
    red_add_v4(((float4*)g_y1) + rc.y * C4 + lane, v);
}

// ---------------- hop 2 (into d_out, bias folded into self-init) ----------------
__global__ void k_self2(float4* __restrict__ out, const float4* __restrict__ b4) {
    int i = blockIdx.x * blockDim.x + threadIdx.x;
    if (i >= N_NODES * C4) return;
    int node = i >> 4, f4 = i & 15;
    float s = g_dinv[node]; s *= s;
    float4 v  = ((const float4*)g_y1)[i];
    float4 bb = b4[f4];
    out[i] = make_float4(fmaf(v.x, s, bb.x), fmaf(v.y, s, bb.y),
                         fmaf(v.z, s, bb.z), fmaf(v.w, s, bb.w));
}

__global__ void k_scat2(float4* __restrict__ out) {
    int t = blockIdx.x * blockDim.x + threadIdx.x;
    int e = t >> 4;
    if (e >= N_EDGES) return;
    int lane = t & 15;
    int2  rc = g_edge[e];
    float nm = g_norm[e];
    float4 v = ((const float4*)g_y1)[rc.x * C4 + lane];
    v.x *= nm; v.y *= nm; v.z *= nm; v.w *= nm;
    red_add_v4(out + rc.y * C4 + lane, v);
}

// ---------------- launch ----------------
extern "C" void kernel_launch(void* const* d_in, const int* in_sizes, int n_in,
                              void* d_out, int out_size) {
    const float* X  = (const float*)d_in[0];
    const void*  EI =               d_in[1];
    const float* W  = (const float*)d_in[2];
    const float* B  = (const float*)d_in[3];
    float4* out = (float4*)d_out;

    const int TB = 256;
    k_detect   <<<1, 1>>>((const int*)EI);
    k_deg_init <<<(N_NODES + TB - 1) / TB, TB>>>();
    k_deg_count<<<(N_EDGES + TB - 1) / TB, TB>>>(EI);
    k_dinv     <<<(N_NODES + TB - 1) / TB, TB>>>();
    k_prep     <<<(N_EDGES + TB - 1) / TB, TB>>>(EI);

    k_gemm<<<N_NODES / 16, 256>>>(X, W);

    int selfGrid = (N_NODES * C4 + TB - 1) / TB;
    int scatGrid = (N_EDGES * 16 + TB - 1) / TB;

    k_self1<<<selfGrid, TB>>>();
    k_scat1<<<scatGrid, TB>>>();
    k_self2<<<selfGrid, TB>>>(out, (const float4*)B);
    k_scat2<<<scatGrid, TB>>>(out);
}

// round 6
// speedup vs baseline: 2.4751x; 2.4751x over previous
#include <cuda_runtime.h>

#define N_NODES   100000
#define N_EDGES   1600000
#define N_FEAT    128
#define N_CLASSES 64
#define C4        (N_CLASSES / 4)         // 16 float4 per node row
#define NBLK      ((N_NODES + 255) / 256) // 391 scan blocks

// ---------------- scratch (device globals; no allocation) ----------------
__device__ int    g_cnt [N_NODES];
__device__ int    g_off [N_NODES];
__device__ int    g_cur [N_NODES];
__device__ int    g_bsum[512];
__device__ float  g_dinv[N_NODES];
__device__ __align__(16) int2  g_ew[N_EDGES];            // (src, bits(norm))
__device__ float4 g_wt4[N_FEAT * C4];                    // Wt[k][c], c-contig
__device__ float4 g_y0 [N_NODES * C4];
__device__ float4 g_y1 [N_NODES * C4];
__device__ int    g_is64;

// ---------------- dtype detection: int64 vs int32 edge_index ----------------
__global__ void k_detect(const int* __restrict__ ei32) {
    int ok = 1;
    #pragma unroll
    for (int i = 1; i < 64; i += 2) ok &= (ei32[i] == 0);
    g_is64 = ok;
}

// ---------------- degree count ----------------
__global__ void k_zero() {
    int i = blockIdx.x * blockDim.x + threadIdx.x;
    if (i < N_NODES) g_cnt[i] = 0;
}

__global__ void k_count(const void* __restrict__ eiv) {
    int e = blockIdx.x * blockDim.x + threadIdx.x;
    if (e >= N_EDGES) return;
    int c;
    if (g_is64) c = (int)((const long long*)eiv)[N_EDGES + e];
    else        c =       ((const int*)      eiv)[N_EDGES + e];
    atomicAdd(&g_cnt[c], 1);
}

__global__ void k_dinv() {
    int i = blockIdx.x * blockDim.x + threadIdx.x;
    if (i < N_NODES) g_dinv[i] = rsqrtf((float)g_cnt[i] + 1.0f); // +1 self-loop
}

// ---------------- exclusive scan (2-level, double-sync Hillis-Steele) ----------------
__global__ void k_scan1() {
    __shared__ int s[256];
    int i = blockIdx.x * 256 + threadIdx.x;
    int v = (i < N_NODES) ? g_cnt[i] : 0;
    int sum = v;
    s[threadIdx.x] = sum;
    __syncthreads();
    #pragma unroll
    for (int off = 1; off < 256; off <<= 1) {
        int t2 = (threadIdx.x >= off) ? s[threadIdx.x - off] : 0;
        __syncthreads();
        sum += t2;
        s[threadIdx.x] = sum;
        __syncthreads();
    }
    if (i < N_NODES) g_off[i] = sum - v;
    if (threadIdx.x == 255) g_bsum[blockIdx.x] = sum;
}

__global__ void k_scan2() {
    __shared__ int s[512];
    int t = threadIdx.x;
    int v = (t < NBLK) ? g_bsum[t] : 0;
    int sum = v;
    s[t] = sum;
    __syncthreads();
    #pragma unroll
    for (int off = 1; off < 512; off <<= 1) {
        int t2 = (t >= off) ? s[t - off] : 0;
        __syncthreads();
        sum += t2;
        s[t] = sum;
        __syncthreads();
    }
    if (t < NBLK) g_bsum[t] = sum - v;
}

__global__ void k_scan3() {
    int i = blockIdx.x * 256 + threadIdx.x;
    if (i >= N_NODES) return;
    int o = g_off[i] + g_bsum[blockIdx.x];
    g_off[i] = o;
    g_cur[i] = o;
}

// ---------------- CSR fill (bounds-clamped) ----------------
__global__ void k_fill(const void* __restrict__ eiv) {
    int e = blockIdx.x * blockDim.x + threadIdx.x;
    if (e >= N_EDGES) return;
    int r, c;
    if (g_is64) {
        const long long* p = (const long long*)eiv;
        r = (int)p[e]; c = (int)p[N_EDGES + e];
    } else {
        const int* p = (const int*)eiv;
        r = p[e];      c = p[N_EDGES + e];
    }
    int pos = atomicAdd(&g_cur[c], 1);
    if (pos >= 0 && pos < N_EDGES)
        g_ew[pos] = make_int2(r, __float_as_int(g_dinv[r] * g_dinv[c]));
}

// ---------------- W transpose: g_wt4[k*16 + c4] = {W[4c..4c+3][k]} ----------------
__global__ void k_wt(const float* __restrict__ W) {
    int i = blockIdx.x * blockDim.x + threadIdx.x;   // over 128*64
    if (i >= N_FEAT * N_CLASSES) return;
    int k = i & 127, c = i >> 7;
    ((float*)g_wt4)[k * N_CLASSES + c] = W[c * N_FEAT + k];
}

// ---------------- GEMM: Y0 = X @ W^T, scalar FMA ----------------
// 64 nodes/block, 256 threads: thread = 4 classes (c16) x 4 nodes (n16).
__global__ __launch_bounds__(256) void k_gemm(const float* __restrict__ X) {
    __shared__ float Xr[64][132];
    const int t = threadIdx.x;
    const int node0 = blockIdx.x * 64;

    for (int i = t; i < 64 * 32; i += 256) {
        int n = i >> 5, k4 = i & 31;
        int node = node0 + n;
        float4 v = (node < N_NODES)
                 ? ((const float4*)(X + (size_t)node * N_FEAT))[k4]
                 : make_float4(0.f, 0.f, 0.f, 0.f);
        *(float4*)&Xr[n][k4 * 4] = v;
    }
    __syncthreads();

    const int c16 = t & 15, n16 = t >> 4;
    float4 acc[4];
    #pragma unroll
    for (int ni = 0; ni < 4; ni++) acc[ni] = make_float4(0.f, 0.f, 0.f, 0.f);

    #pragma unroll 4
    for (int k = 0; k < N_FEAT; k++) {
        float4 wv = __ldg(&g_wt4[k * 16 + c16]);
        #pragma unroll
        for (int ni = 0; ni < 4; ni++) {
            float x = Xr[n16 * 4 + ni][k];
            acc[ni].x = fmaf(x, wv.x, acc[ni].x);
            acc[ni].y = fmaf(x, wv.y, acc[ni].y);
            acc[ni].z = fmaf(x, wv.z, acc[ni].z);
            acc[ni].w = fmaf(x, wv.w, acc[ni].w);
        }
    }

    #pragma unroll
    for (int ni = 0; ni < 4; ni++) {
        int node = node0 + n16 * 4 + ni;
        if (node < N_NODES)
            g_y0[(size_t)node * C4 + c16] = acc[ni];
    }
}

// ---------------- propagation hops ----------------
// Device-side accumulate body shared by both hops. `in` is a DEVICE-resolved
// pointer (global symbol referenced inside device code), never a host-passed
// device-symbol address.
__device__ __forceinline__ float4 hop_accum(const float4* __restrict__ in,
                                            int node, int lane, float4 acc) {
    int j   = g_off[node];
    int end = j + g_cnt[node];
    if (end > N_EDGES) end = N_EDGES;   // defensive

    for (; j + 1 < end; j += 2) {
        int2 e0 = __ldg(&g_ew[j]);
        int2 e1 = __ldg(&g_ew[j + 1]);
        float w0 = __int_as_float(e0.y);
        float w1 = __int_as_float(e1.y);
        float4 u0 = __ldg(&in[(size_t)e0.x * C4 + lane]);
        float4 u1 = __ldg(&in[(size_t)e1.x * C4 + lane]);
        acc.x = fmaf(w0, u0.x, acc.x); acc.y = fmaf(w0, u0.y, acc.y);
        acc.z = fmaf(w0, u0.z, acc.z); acc.w = fmaf(w0, u0.w, acc.w);
        acc.x = fmaf(w1, u1.x, acc.x); acc.y = fmaf(w1, u1.y, acc.y);
        acc.z = fmaf(w1, u1.z, acc.z); acc.w = fmaf(w1, u1.w, acc.w);
    }
    if (j < end) {
        int2 e0 = __ldg(&g_ew[j]);
        float w0 = __int_as_float(e0.y);
        float4 u0 = __ldg(&in[(size_t)e0.x * C4 + lane]);
        acc.x = fmaf(w0, u0.x, acc.x); acc.y = fmaf(w0, u0.y, acc.y);
        acc.z = fmaf(w0, u0.z, acc.z); acc.w = fmaf(w0, u0.w, acc.w);
    }
    return acc;
}

__global__ void k_hop1() {   // g_y1 = P(g_y0)
    int t = blockIdx.x * blockDim.x + threadIdx.x;
    int node = t >> 4;
    if (node >= N_NODES) return;
    int lane = t & 15;

    float dv = g_dinv[node];
    float s = dv * dv;
    float4 v = g_y0[(size_t)node * C4 + lane];
    float4 acc = make_float4(v.x * s, v.y * s, v.z * s, v.w * s);
    acc = hop_accum(g_y0, node, lane, acc);
    g_y1[(size_t)node * C4 + lane] = acc;
}

__global__ void k_hop2(float4* __restrict__ out,
                       const float4* __restrict__ bias) {  // out = P(g_y1) + b
    int t = blockIdx.x * blockDim.x + threadIdx.x;
    int node = t >> 4;
    if (node >= N_NODES) return;
    int lane = t & 15;

    float dv = g_dinv[node];
    float s = dv * dv;
    float4 v  = g_y1[(size_t)node * C4 + lane];
    float4 bb = __ldg(&bias[lane]);
    float4 acc = make_float4(fmaf(v.x, s, bb.x), fmaf(v.y, s, bb.y),
                             fmaf(v.z, s, bb.z), fmaf(v.w, s, bb.w));
    acc = hop_accum(g_y1, node, lane, acc);
    out[(size_t)node * C4 + lane] = acc;
}

// ---------------- launch ----------------
extern "C" void kernel_launch(void* const* d_in, const int* in_sizes, int n_in,
                              void* d_out, int out_size) {
    const float* X  = (const float*)d_in[0];
    const void*  EI =               d_in[1];
    const float* W  = (const float*)d_in[2];
    const float* B  = (const float*)d_in[3];

    const int TB = 256;
    const int gN = (N_NODES + TB - 1) / TB;
    const int gE = (N_EDGES + TB - 1) / TB;

    k_detect<<<1, 1>>>((const int*)EI);
    k_zero  <<<gN, TB>>>();
    k_count <<<gE, TB>>>(EI);
    k_dinv  <<<gN, TB>>>();
    k_scan1 <<<NBLK, 256>>>();
    k_scan2 <<<1, 512>>>();
    k_scan3 <<<NBLK, 256>>>();
    k_fill  <<<gE, TB>>>(EI);

    k_wt    <<<(N_FEAT * N_CLASSES + TB - 1) / TB, TB>>>(W);
    k_gemm  <<<(N_NODES + 63) / 64, 256>>>(X);

    int gH = (N_NODES * 16 + TB - 1) / TB;
    k_hop1<<<gH, TB>>>();
    k_hop2<<<gH, TB>>>((float4*)d_out, (const float4*)B);
}

// round 7
// speedup vs baseline: 2.7008x; 1.0912x over previous
#include <cuda_runtime.h>

#define N_NODES   100000
#define N_EDGES   1600000
#define N_FEAT    128
#define N_CLASSES 64
#define C4        (N_CLASSES / 4)         // 16 float4 per node row
#define NBLK      ((N_NODES + 255) / 256) // 391 scan blocks
#define GEMM_BLKS ((N_NODES + 63) / 64)   // 1563
#define GE_BLKS   ((N_EDGES + 255) / 256) // 6250
#define WT_BLKS   ((N_FEAT * N_CLASSES + 255) / 256) // 32

// ---------------- scratch (device globals; no allocation) ----------------
__device__ int    g_cnt [N_NODES];
__device__ int    g_off [N_NODES];
__device__ int    g_cur [N_NODES];
__device__ int    g_bsum[512];
__device__ float  g_dinv[N_NODES];
__device__ __align__(16) int2  g_ew[N_EDGES];            // (src, bits(norm))
__device__ float4 g_wt4[N_FEAT * C4];                    // Wt[k][c], c-contig
__device__ float4 g_y0 [N_NODES * C4];
__device__ float4 g_y1 [N_NODES * C4];
__device__ int    g_is64;

// ---------------- init: zero counts + dtype detect ----------------
__global__ void k_init(const int* __restrict__ ei32) {
    int i = blockIdx.x * blockDim.x + threadIdx.x;
    if (i < N_NODES) g_cnt[i] = 0;
    if (i == 0) {
        int ok = 1;
        #pragma unroll
        for (int j = 1; j < 64; j += 2) ok &= (ei32[j] == 0);
        g_is64 = ok;
    }
}

// ---------------- count + W transpose (stitched grid) ----------------
__global__ void k_cw(const void* __restrict__ eiv, const float* __restrict__ W) {
    if (blockIdx.x < GE_BLKS) {
        int e = blockIdx.x * blockDim.x + threadIdx.x;
        if (e >= N_EDGES) return;
        int c;
        if (g_is64) c = (int)((const long long*)eiv)[N_EDGES + e];
        else        c =       ((const int*)      eiv)[N_EDGES + e];
        atomicAdd(&g_cnt[c], 1);
    } else {
        int i = (blockIdx.x - GE_BLKS) * blockDim.x + threadIdx.x;
        if (i >= N_FEAT * N_CLASSES) return;
        int k = i & 127, c = i >> 7;
        ((float*)g_wt4)[k * N_CLASSES + c] = W[c * N_FEAT + k];
    }
}

// ---------------- scan level 1 (+ dinv fused) ----------------
__global__ void k_scan1() {
    __shared__ int s[256];
    int i = blockIdx.x * 256 + threadIdx.x;
    int v = (i < N_NODES) ? g_cnt[i] : 0;
    if (i < N_NODES) g_dinv[i] = rsqrtf((float)v + 1.0f);  // +1 self-loop
    int sum = v;
    s[threadIdx.x] = sum;
    __syncthreads();
    #pragma unroll
    for (int off = 1; off < 256; off <<= 1) {
        int t2 = (threadIdx.x >= off) ? s[threadIdx.x - off] : 0;
        __syncthreads();
        sum += t2;
        s[threadIdx.x] = sum;
        __syncthreads();
    }
    if (i < N_NODES) g_off[i] = sum - v;
    if (threadIdx.x == 255) g_bsum[blockIdx.x] = sum;
}

__global__ void k_scan2() {
    __shared__ int s[512];
    int t = threadIdx.x;
    int v = (t < NBLK) ? g_bsum[t] : 0;
    int sum = v;
    s[t] = sum;
    __syncthreads();
    #pragma unroll
    for (int off = 1; off < 512; off <<= 1) {
        int t2 = (t >= off) ? s[t - off] : 0;
        __syncthreads();
        sum += t2;
        s[t] = sum;
        __syncthreads();
    }
    if (t < NBLK) g_bsum[t] = sum - v;
}

__global__ void k_scan3() {
    int i = blockIdx.x * 256 + threadIdx.x;
    if (i >= N_NODES) return;
    int o = g_off[i] + g_bsum[blockIdx.x];
    g_off[i] = o;
    g_cur[i] = o;
}

// ---------------- stitched: GEMM (blocks [0,GEMM_BLKS)) + CSR fill ----------------
// GEMM: Y0 = X @ W^T via packed fma.rn.f32x2 (FFMA2 — PTX-only form).
// Thread = 4 classes (c16) x 4 nodes (n16); 64 nodes/block.
__global__ __launch_bounds__(256) void k_fg(const void* __restrict__ eiv,
                                            const float* __restrict__ X) {
    __shared__ float Xr[64][132];
    if (blockIdx.x < GEMM_BLKS) {
        const int t = threadIdx.x;
        const int node0 = blockIdx.x * 64;

        for (int i = t; i < 64 * 32; i += 256) {
            int n = i >> 5, k4 = i & 31;
            int node = node0 + n;
            float4 v = (node < N_NODES)
                     ? ((const float4*)(X + (size_t)node * N_FEAT))[k4]
                     : make_float4(0.f, 0.f, 0.f, 0.f);
            *(float4*)&Xr[n][k4 * 4] = v;
        }
        __syncthreads();

        const int c16 = t & 15, n16 = t >> 4;
        unsigned long long a01[4], a23[4];
        #pragma unroll
        for (int ni = 0; ni < 4; ni++) { a01[ni] = 0ull; a23[ni] = 0ull; }

        #pragma unroll 4
        for (int k = 0; k < N_FEAT; k++) {
            float4 wv = __ldg(&g_wt4[k * 16 + c16]);
            unsigned long long w01, w23;
            asm("mov.b64 %0, {%1,%2};" : "=l"(w01) : "f"(wv.x), "f"(wv.y));
            asm("mov.b64 %0, {%1,%2};" : "=l"(w23) : "f"(wv.z), "f"(wv.w));
            #pragma unroll
            for (int ni = 0; ni < 4; ni++) {
                float x = Xr[n16 * 4 + ni][k];
                unsigned long long xx;
                asm("mov.b64 %0, {%1,%1};" : "=l"(xx) : "f"(x));
                asm("fma.rn.f32x2 %0, %1, %2, %0;" : "+l"(a01[ni]) : "l"(xx), "l"(w01));
                asm("fma.rn.f32x2 %0, %1, %2, %0;" : "+l"(a23[ni]) : "l"(xx), "l"(w23));
            }
        }

        #pragma unroll
        for (int ni = 0; ni < 4; ni++) {
            int node = node0 + n16 * 4 + ni;
            if (node < N_NODES) {
                float r0, r1, r2, r3;
                asm("mov.b64 {%0,%1}, %2;" : "=f"(r0), "=f"(r1) : "l"(a01[ni]));
                asm("mov.b64 {%0,%1}, %2;" : "=f"(r2), "=f"(r3) : "l"(a23[ni]));
                g_y0[(size_t)node * C4 + c16] = make_float4(r0, r1, r2, r3);
            }
        }
    } else {
        // CSR fill
        int e = (blockIdx.x - GEMM_BLKS) * blockDim.x + threadIdx.x;
        if (e >= N_EDGES) return;
        int r, c;
        if (g_is64) {
            const long long* p = (const long long*)eiv;
            r = (int)p[e]; c = (int)p[N_EDGES + e];
        } else {
            const int* p = (const int*)eiv;
            r = p[e];      c = p[N_EDGES + e];
        }
        int pos = atomicAdd(&g_cur[c], 1);
        if (pos >= 0 && pos < N_EDGES)
            g_ew[pos] = make_int2(r, __float_as_int(g_dinv[r] * g_dinv[c]));
    }
}

// ---------------- propagation hops (unroll 4, front-batched loads) ----------------
__device__ __forceinline__ float4 hop_accum(const float4* __restrict__ in,
                                            int node, int lane, float4 acc) {
    int j   = g_off[node];
    int end = j + g_cnt[node];
    if (end > N_EDGES) end = N_EDGES;   // defensive

    for (; j + 3 < end; j += 4) {
        int2 e0 = __ldg(&g_ew[j]);
        int2 e1 = __ldg(&g_ew[j + 1]);
        int2 e2 = __ldg(&g_ew[j + 2]);
        int2 e3 = __ldg(&g_ew[j + 3]);
        float4 u0 = __ldg(&in[(size_t)e0.x * C4 + lane]);
        float4 u1 = __ldg(&in[(size_t)e1.x * C4 + lane]);
        float4 u2 = __ldg(&in[(size_t)e2.x * C4 + lane]);
        float4 u3 = __ldg(&in[(size_t)e3.x * C4 + lane]);
        float w0 = __int_as_float(e0.y), w1 = __int_as_float(e1.y);
        float w2 = __int_as_float(e2.y), w3 = __int_as_float(e3.y);
        acc.x = fmaf(w0, u0.x, acc.x); acc.y = fmaf(w0, u0.y, acc.y);
        acc.z = fmaf(w0, u0.z, acc.z); acc.w = fmaf(w0, u0.w, acc.w);
        acc.x = fmaf(w1, u1.x, acc.x); acc.y = fmaf(w1, u1.y, acc.y);
        acc.z = fmaf(w1, u1.z, acc.z); acc.w = fmaf(w1, u1.w, acc.w);
        acc.x = fmaf(w2, u2.x, acc.x); acc.y = fmaf(w2, u2.y, acc.y);
        acc.z = fmaf(w2, u2.z, acc.z); acc.w = fmaf(w2, u2.w, acc.w);
        acc.x = fmaf(w3, u3.x, acc.x); acc.y = fmaf(w3, u3.y, acc.y);
        acc.z = fmaf(w3, u3.z, acc.z); acc.w = fmaf(w3, u3.w, acc.w);
    }
    for (; j < end; j++) {
        int2 e0 = __ldg(&g_ew[j]);
        float w0 = __int_as_float(e0.y);
        float4 u0 = __ldg(&in[(size_t)e0.x * C4 + lane]);
        acc.x = fmaf(w0, u0.x, acc.x); acc.y = fmaf(w0, u0.y, acc.y);
        acc.z = fmaf(w0, u0.z, acc.z); acc.w = fmaf(w0, u0.w, acc.w);
    }
    return acc;
}

__global__ void k_hop1() {   // g_y1 = P(g_y0)
    int t = blockIdx.x * blockDim.x + threadIdx.x;
    int node = t >> 4;
    if (node >= N_NODES) return;
    int lane = t & 15;

    float dv = g_dinv[node];
    float s = dv * dv;
    float4 v = g_y0[(size_t)node * C4 + lane];
    float4 acc = make_float4(v.x * s, v.y * s, v.z * s, v.w * s);
    acc = hop_accum(g_y0, node, lane, acc);
    g_y1[(size_t)node * C4 + lane] = acc;
}

__global__ void k_hop2(float4* __restrict__ out,
                       const float4* __restrict__ bias) {  // out = P(g_y1) + b
    int t = blockIdx.x * blockDim.x + threadIdx.x;
    int node = t >> 4;
    if (node >= N_NODES) return;
    int lane = t & 15;

    float dv = g_dinv[node];
    float s = dv * dv;
    float4 v  = g_y1[(size_t)node * C4 + lane];
    float4 bb = __ldg(&bias[lane]);
    float4 acc = make_float4(fmaf(v.x, s, bb.x), fmaf(v.y, s, bb.y),
                             fmaf(v.z, s, bb.z), fmaf(v.w, s, bb.w));
    acc = hop_accum(g_y1, node, lane, acc);
    out[(size_t)node * C4 + lane] = acc;
}

// ---------------- launch ----------------
extern "C" void kernel_launch(void* const* d_in, const int* in_sizes, int n_in,
                              void* d_out, int out_size) {
    const float* X  = (const float*)d_in[0];
    const void*  EI =               d_in[1];
    const float* W  = (const float*)d_in[2];
    const float* B  = (const float*)d_in[3];

    const int TB = 256;
    const int gN = (N_NODES + TB - 1) / TB;

    k_init <<<gN, TB>>>((const int*)EI);
    k_cw   <<<GE_BLKS + WT_BLKS, TB>>>(EI, W);
    k_scan1<<<NBLK, 256>>>();
    k_scan2<<<1, 512>>>();
    k_scan3<<<NBLK, 256>>>();
    k_fg   <<<GEMM_BLKS + GE_BLKS, TB>>>(EI, X);

    int gH = (N_NODES * 16 + TB - 1) / TB;
    k_hop1<<<gH, TB>>>();
    k_hop2<<<gH, TB>>>((float4*)d_out, (const float4*)B);
}